// round 16
// baseline (speedup 1.0000x reference)
#include <cuda_runtime.h>

// EdgeBlock, two sequential launches of individually-proven kernels.
// B=4, L=1024, N=16, D=64, W=16, V=33.
//
// R9-R15 lesson: every attempt to co-schedule score and value CTAs in one
// launch pins DRAM at ~50% and costs ~30us that no pipe metric explains.
// Decision: stop fusing. Launch the fast score kernel (R13 path, ~15-30us,
// also warms L2 with hidden), then the value kernel in its PROVEN standalone
// config (R6: 8-l tiles, 24 staged rows, 96KB smem, plain stores - measured
// 88.5us @ 5764 GB/s).
//
// Outputs (concatenated fp32 in d_out):
//   window_score (B,N,L,V)   = 2,162,688 floats
//   value_h      (B,L,V,N,D) = 138,412,032 floats (553 MB, DRAM-write bound)

#define Lc 1024
#define MASK_FILL -1e12f

// ---------------------------------------------------------------------------
// Score kernel: one block per (b, n, 128-l tile). 256 threads, 63 KB smem,
// 3 CTAs/SM. Shuffle-reduction Phase B, 17 deduplicated window products.
// ---------------------------------------------------------------------------
__global__ void __launch_bounds__(256, 3) score_kernel(
    const float* __restrict__ hidden,
    const int*   __restrict__ mask,
    const float* __restrict__ upon,
    const float* __restrict__ down,
    const float* __restrict__ cross,
    float*       __restrict__ out_ws)
{
    extern __shared__ float sm[];
    const int t = threadIdx.x;
    const int s = blockIdx.x;
    const int tile = s & 7, n = (s >> 3) & 15, b = s >> 7;
    const int l0 = tile * 128;

    float* shC  = sm;             // [64][68]  (cross transposed: shC[h*68+d])
    float* shH  = sm + 4352;      // [160][68] (rows l0-16 .. l0+143, wrapped)
    float* su   = sm + 15232;     // [160]
    float* sd   = sm + 15392;     // [160]
    float* shup = sm + 15552;     // [64]
    float* shdn = sm + 15616;     // [64]
    int*   shm  = (int*)(sm + 15680); // [160]
    // 15,840 floats = 63,360 B -> 3 CTAs/SM

    for (int i = t; i < 4096; i += 256) {
        int d2 = i >> 6, h2 = i & 63;
        shC[h2 * 68 + d2] = cross[n * 4096 + i];
    }
    if (t < 64) { shup[t] = upon[n * 64 + t]; shdn[t] = down[n * 64 + t]; }

    {
        const float4* h4 = (const float4*)hidden;
        for (int i = t; i < 2560; i += 256) {         // 160 rows * 16 quads
            int rr = i >> 4, dq = i & 15;
            int row = (l0 - 16 + rr) & (Lc - 1);
            float4 v = h4[(((size_t)(b << 10) + row) * 16 + n) * 16 + dq];
            *(float4*)&shH[rr * 68 + dq * 4] = v;
        }
    }
    if (t < 160) shm[t] = mask[(b << 10) + ((l0 + t) & (Lc - 1))];
    __syncthreads();

    if (t < 160) {
        const float* hr = &shH[t * 68];
        float a = 0.f, c = 0.f;
#pragma unroll
        for (int dq = 0; dq < 16; ++dq) {
            float4 hv = *(const float4*)&hr[dq * 4];
            float4 up = *(const float4*)&shup[dq * 4];
            float4 dn = *(const float4*)&shdn[dq * 4];
            a += hv.x * up.x + hv.y * up.y + hv.z * up.z + hv.w * up.w;
            c += hv.x * dn.x + hv.y * dn.y + hv.z * dn.z + hv.w * dn.w;
        }
        su[t] = a; sd[t] = c;
    }
    __syncthreads();

    const int w = t >> 5, lane = t & 31;

    for (int g = 0; g < 2; ++g) {
        const int lloc0 = w * 16 + g * 8;   // 8 consecutive l's per group
        const int rb    = lloc0 + 16;       // shH row of first l

        // Phase A: qc[i][h] for 8 l's; lane owns h=lane, h=lane+32.
        float a0[8] = {0,0,0,0,0,0,0,0}, a1[8] = {0,0,0,0,0,0,0,0};
#pragma unroll
        for (int dq = 0; dq < 16; ++dq) {
            float4 c0 = *(const float4*)&shC[lane * 68 + dq * 4];
            float4 c1 = *(const float4*)&shC[(lane + 32) * 68 + dq * 4];
#pragma unroll
            for (int i = 0; i < 8; ++i) {
                float4 hd = *(const float4*)&shH[(rb + i) * 68 + dq * 4];
                a0[i] += hd.x * c0.x + hd.y * c0.y + hd.z * c0.z + hd.w * c0.w;
                a1[i] += hd.x * c1.x + hd.y * c1.y + hd.z * c1.z + hd.w * c1.w;
            }
        }

        // Phase B: 17 window products per l via shuffle reduction.
        float pk[8];
#pragma unroll
        for (int i = 0; i < 8; ++i) {
            pk[i] = 0.f;
            for (int o = 0; o < 17; ++o) {
                const float* hr = &shH[(rb + i + o) * 68];
                float p = a0[i] * hr[lane] + a1[i] * hr[lane + 32];
#pragma unroll
                for (int d2 = 16; d2 > 0; d2 >>= 1)
                    p += __shfl_xor_sync(0xffffffffu, p, d2);
                if (lane == o) pk[i] = p;
            }
        }

        // Assembly: 33 scores per l.
#pragma unroll
        for (int i = 0; i < 8; ++i) {
            const int lloc = lloc0 + i, l = l0 + lloc, rbl = rb + i;
            size_t ob = ((size_t)((b * 16 + n) * Lc + l)) * 33;

            {
                int v = lane;
                int offu = (v <= 16) ? 0 : (v - 16);
                int offd = (v <  16) ? (v - 16) : 0;
                float prod = __shfl_sync(0xffffffffu, pk[i], offu);
                float sc = prod + su[rbl + offu] + sd[rbl + offd];
                sc = (sc > 0.f) ? sc : 5.0f * sc;           // leaky_relu slope 5
                bool m = (l + offd >= 0) && (l + offu < Lc) &&
                         (shm[lloc + offu] != 0);
                out_ws[ob + v] = m ? sc : MASK_FILL;
            }
            {
                float prod32 = __shfl_sync(0xffffffffu, pk[i], 16);
                if (lane == 0) {
                    float sc = prod32 + su[rbl + 16] + sd[rbl];
                    sc = (sc > 0.f) ? sc : 5.0f * sc;
                    bool m = (l + 16 < Lc) && (shm[lloc + 16] != 0);
                    out_ws[ob + 32] = m ? sc : MASK_FILL;
                }
            }
        }
    }
}

// ---------------------------------------------------------------------------
// Value gather: R6 standalone config verbatim (measured 88.5us, 5764 GB/s).
// One block per (b, 8-l tile). 24 staged rows (96 KB), 2 CTAs/SM.
// ---------------------------------------------------------------------------
__global__ void value_kernel(const float4* __restrict__ hidden4,
                             float4* __restrict__ out4) {
    extern __shared__ float4 sh4[];       // 24 * 256 float4 = 96 KB
    const int t  = threadIdx.x;           // 256
    const int b  = blockIdx.y;
    const int l0 = blockIdx.x * 8;

#pragma unroll
    for (int r = 0; r < 24; ++r) {
        int row = (l0 + r) & (Lc - 1);
        sh4[r * 256 + t] = hidden4[((size_t)b * Lc + row) * 256 + t];
    }
    __syncthreads();

    for (int ll = 0; ll < 8; ++ll) {
        size_t base = ((size_t)(b * Lc + l0 + ll)) * 33 * 256 + t;
#pragma unroll
        for (int v = 0; v < 33; ++v) {
            int off = (v <= 16) ? 0 : (v - 16);
            out4[base + (size_t)v * 256] = sh4[(ll + off) * 256 + t];
        }
    }
}

extern "C" void kernel_launch(void* const* d_in, const int* in_sizes, int n_in,
                              void* d_out, int out_size) {
    const float* hidden = (const float*)d_in[0];
    const int*   mask   = (const int*)d_in[1];      // bool -> int32 on the wire
    const float* upon   = (const float*)d_in[2];
    const float* down   = (const float*)d_in[3];
    const float* cross  = (const float*)d_in[4];
    // d_in[5] (window_size) fixed at 16; compiled in.

    float*  out_ws  = (float*)d_out;
    float4* out_val = (float4*)(out_ws + (size_t)4 * 16 * Lc * 33); // 2,162,688 floats

    const int smemS = 15840 * (int)sizeof(float);      // 63,360 B -> 3 CTAs/SM
    const int smemV = 24 * 256 * (int)sizeof(float4);  // 98,304 B -> 2 CTAs/SM
    cudaFuncSetAttribute(score_kernel, cudaFuncAttributeMaxDynamicSharedMemorySize, smemS);
    cudaFuncSetAttribute(value_kernel, cudaFuncAttributeMaxDynamicSharedMemorySize, smemV);

    // Score first (short; also warms L2 with hidden), then the proven value
    // kernel in isolation so its write stream owns the whole chip.
    score_kernel<<<512, 256, smemS>>>(hidden, mask, upon, down, cross, out_ws);

    dim3 gv(Lc / 8, 4);                   // 128 x 4 = 512 blocks
    value_kernel<<<gv, 256, smemV>>>((const float4*)hidden, out_val);
}

// round 17
// speedup vs baseline: 1.1807x; 1.1807x over previous
#include <cuda_runtime.h>

// EdgeBlock fused, R10 structure + latency-fixed Phase B.
// B=4, L=1024, N=16, D=64, W=16, V=33.
//
// R16 datum: score standalone = 65.8us (vs ~15us FMA floor) -> Phase B's 272
// serially-dependent 5-step shuffle butterflies per warp (~190cyc each) are
// the bottleneck. Fix: 4 independent o-chains in flight per block (o-blocks
// {0-3},{4-7},{8-11},{12-15},{16}), unconditional all-lane butterflies,
// predicated commit. ~4x less Phase-B critical path.
//
// Value path byte-identical to the proven 5764 GB/s config (R6/R10):
// 8-l tiles, 24 staged rows, 96 KB smem, __stcs. 1:1 CTA interleave (best
// measured fusion structure: R10 = 120.4us).
//
// Outputs (concatenated fp32 in d_out):
//   window_score (B,N,L,V)   = 2,162,688 floats
//   value_h      (B,L,V,N,D) = 138,412,032 floats (553 MB, DRAM-write bound)

#define Lc 1024
#define MASK_FILL -1e12f

__global__ void __launch_bounds__(256, 2) fused_kernel(
    const float* __restrict__ hidden,
    const int*   __restrict__ mask,
    const float* __restrict__ upon,
    const float* __restrict__ down,
    const float* __restrict__ cross,
    float*       __restrict__ out_ws,
    float4*      __restrict__ out_val)
{
    extern __shared__ float sm[];
    const int t   = threadIdx.x;
    const int bid = blockIdx.x;
    const int s   = bid >> 1;               // 0..511 within each class

    if ((bid & 1) == 0) {
        // ------------- value path: 8-l tile, 24 staged rows (96 KB) -------------
        float4* sh4 = (float4*)sm;
        const int b  = s >> 7;               // 0..3
        const int l0 = (s & 127) * 8;
        const float4* hidden4 = (const float4*)hidden;

#pragma unroll
        for (int r = 0; r < 24; ++r) {
            int row = (l0 + r) & (Lc - 1);
            sh4[r * 256 + t] = hidden4[((size_t)(b << 10) + row) * 256 + t];
        }
        __syncthreads();

        for (int ll = 0; ll < 8; ++ll) {
            size_t base = ((size_t)((b << 10) + l0 + ll)) * 33 * 256 + t;
#pragma unroll
            for (int v = 0; v < 33; ++v) {
                int off = (v <= 16) ? 0 : (v - 16);
                __stcs(&out_val[base + (size_t)v * 256], sh4[(ll + off) * 256 + t]);
            }
        }
        return;
    }

    // ------------------------- score path: s in 0..511 -------------------------
    const int tile = s & 7, n = (s >> 3) & 15, b = s >> 7;
    const int l0 = tile * 128;

    float* shC  = sm;             // [64][68]  (cross transposed: shC[h*68+d])
    float* shH  = sm + 4352;      // [160][68] (rows l0-16 .. l0+143, wrapped)
    float* su   = sm + 15232;     // [160]
    float* sd   = sm + 15392;     // [160]
    float* shup = sm + 15552;     // [64]
    float* shdn = sm + 15616;     // [64]
    int*   shm  = (int*)(sm + 15680); // [160]

    for (int i = t; i < 4096; i += 256) {
        int d2 = i >> 6, h2 = i & 63;
        shC[h2 * 68 + d2] = cross[n * 4096 + i];
    }
    if (t < 64) { shup[t] = upon[n * 64 + t]; shdn[t] = down[n * 64 + t]; }

    {
        const float4* h4 = (const float4*)hidden;
        for (int i = t; i < 2560; i += 256) {         // 160 rows * 16 quads
            int rr = i >> 4, dq = i & 15;
            int row = (l0 - 16 + rr) & (Lc - 1);
            float4 v = h4[(((size_t)(b << 10) + row) * 16 + n) * 16 + dq];
            *(float4*)&shH[rr * 68 + dq * 4] = v;
        }
    }
    if (t < 160) shm[t] = mask[(b << 10) + ((l0 + t) & (Lc - 1))];
    __syncthreads();

    if (t < 160) {
        const float* hr = &shH[t * 68];
        float a = 0.f, c = 0.f;
#pragma unroll
        for (int dq = 0; dq < 16; ++dq) {
            float4 hv = *(const float4*)&hr[dq * 4];
            float4 up = *(const float4*)&shup[dq * 4];
            float4 dn = *(const float4*)&shdn[dq * 4];
            a += hv.x * up.x + hv.y * up.y + hv.z * up.z + hv.w * up.w;
            c += hv.x * dn.x + hv.y * dn.y + hv.z * dn.z + hv.w * dn.w;
        }
        su[t] = a; sd[t] = c;
    }
    __syncthreads();

    const int w = t >> 5, lane = t & 31;

    for (int g = 0; g < 2; ++g) {
        const int lloc0 = w * 16 + g * 8;   // 8 consecutive l's per group
        const int rb    = lloc0 + 16;       // shH row of first l

        // Phase A: qc[i][h] for 8 l's; lane owns h=lane, h=lane+32.
        float a0[8] = {0,0,0,0,0,0,0,0}, a1[8] = {0,0,0,0,0,0,0,0};
#pragma unroll
        for (int dq = 0; dq < 16; ++dq) {
            float4 c0 = *(const float4*)&shC[lane * 68 + dq * 4];
            float4 c1 = *(const float4*)&shC[(lane + 32) * 68 + dq * 4];
#pragma unroll
            for (int i = 0; i < 8; ++i) {
                float4 hd = *(const float4*)&shH[(rb + i) * 68 + dq * 4];
                a0[i] += hd.x * c0.x + hd.y * c0.y + hd.z * c0.z + hd.w * c0.w;
                a1[i] += hd.x * c1.x + hd.y * c1.y + hd.z * c1.z + hd.w * c1.w;
            }
        }

        // Phase B: 17 window products per l. 4 INDEPENDENT butterfly chains
        // in flight per o-block to break shuffle-latency serialization.
        float pk[8];
#pragma unroll
        for (int i = 0; i < 8; ++i) {
            pk[i] = 0.f;
#pragma unroll
            for (int ob = 0; ob < 20; ob += 4) {
                float p[4];
#pragma unroll
                for (int j = 0; j < 4; ++j) {
                    int o = ob + j;
                    if (o < 17) {
                        const float* hr = &shH[(rb + i + o) * 68];
                        p[j] = a0[i] * hr[lane] + a1[i] * hr[lane + 32];
                    } else {
                        p[j] = 0.f;
                    }
                }
                // interleaved butterflies: 4 independent chains
#pragma unroll
                for (int d2 = 16; d2 > 0; d2 >>= 1) {
#pragma unroll
                    for (int j = 0; j < 4; ++j)
                        p[j] += __shfl_xor_sync(0xffffffffu, p[j], d2);
                }
#pragma unroll
                for (int j = 0; j < 4; ++j) {
                    int o = ob + j;
                    if (o < 17 && lane == o) pk[i] = p[j];
                }
            }
        }

        // Assembly: 33 scores per l.
#pragma unroll
        for (int i = 0; i < 8; ++i) {
            const int lloc = lloc0 + i, l = l0 + lloc, rbl = rb + i;
            size_t ob2 = ((size_t)((b * 16 + n) * Lc + l)) * 33;

            {
                int v = lane;
                int offu = (v <= 16) ? 0 : (v - 16);
                int offd = (v <  16) ? (v - 16) : 0;
                float prod = __shfl_sync(0xffffffffu, pk[i], offu);
                float sc = prod + su[rbl + offu] + sd[rbl + offd];
                sc = (sc > 0.f) ? sc : 5.0f * sc;           // leaky_relu slope 5
                bool m = (l + offd >= 0) && (l + offu < Lc) &&
                         (shm[lloc + offu] != 0);
                __stcs(&out_ws[ob2 + v], m ? sc : MASK_FILL);
            }
            {
                float prod32 = __shfl_sync(0xffffffffu, pk[i], 16);
                if (lane == 0) {
                    float sc = prod32 + su[rbl + 16] + sd[rbl];
                    sc = (sc > 0.f) ? sc : 5.0f * sc;
                    bool m = (l + 16 < Lc) && (shm[lloc + 16] != 0);
                    __stcs(&out_ws[ob2 + 32], m ? sc : MASK_FILL);
                }
            }
        }
    }
}

extern "C" void kernel_launch(void* const* d_in, const int* in_sizes, int n_in,
                              void* d_out, int out_size) {
    const float* hidden = (const float*)d_in[0];
    const int*   mask   = (const int*)d_in[1];      // bool -> int32 on the wire
    const float* upon   = (const float*)d_in[2];
    const float* down   = (const float*)d_in[3];
    const float* cross  = (const float*)d_in[4];
    // d_in[5] (window_size) fixed at 16; compiled in.

    float*  out_ws  = (float*)d_out;
    float4* out_val = (float4*)(out_ws + (size_t)4 * 16 * Lc * 33); // 2,162,688 floats

    const int smem = 24 * 256 * (int)sizeof(float4);   // 98,304 B (value path max)
    cudaFuncSetAttribute(fused_kernel, cudaFuncAttributeMaxDynamicSharedMemorySize, smem);

    // 1024 blocks, 1:1 interleave: even bid = value, odd bid = score.
    fused_kernel<<<1024, 256, smem>>>(hidden, mask, upon, down, cross,
                                      out_ws, out_val);
}